// round 13
// baseline (speedup 1.0000x reference)
#include <cuda_runtime.h>
#include <math.h>

#define IMG_W 256
#define IMG_H 256
#define NPIX  (IMG_W * IMG_H)
#define GAB   4
#define NBLK  128
#define NTHR  512
#define TCUT  10.0f

// Static scratch — zero at module load; kernel restores zeros each run.
__device__ float4 d_acc[NPIX];       // RGBA accumulator (A unused)
__device__ int d_work;               // dynamic pair ticket counter
__device__ int d_cnt32[32];
__device__ int d_done;

__device__ __forceinline__ void red_add_v4(float4* addr, float r, float g, float b)
{
    asm volatile("red.global.add.v4.f32 [%0], {%1, %2, %3, %4};"
                 :: "l"(addr), "f"(r), "f"(g), "f"(b), "f"(0.0f)
                 : "memory");
}

__global__ __launch_bounds__(NTHR, 1)
void fused_splat_kernel(const float* __restrict__ lmu, const float* __restrict__ lch,
                        const float* __restrict__ lft, const float* __restrict__ lop,
                        const float* __restrict__ hmu, const float* __restrict__ hch,
                        const float* __restrict__ hft, const float* __restrict__ hop,
                        const float* __restrict__ gfreq, const float* __restrict__ gwt,
                        int nl, int nh, float* __restrict__ out)
{
    const int tid   = threadIdx.x;
    const int blk   = blockIdx.x;
    const int gtid  = blk * NTHR + tid;
    const int lane  = tid & 31;
    const int half  = lane >> 4;
    const int hlane = lane & 15;
    const int ntot  = nl + nh;
    const int npairs = (ntot + 1) >> 1;
    const unsigned FULL = 0xffffffffu;

    // ------------- Phase 1: dynamic work-stealing, half-warp per splat -------------
    int pid;
    if (lane == 0) pid = atomicAdd(&d_work, 1);
    pid = __shfl_sync(FULL, pid, 0);

    while (pid < npairs) {
        // Pipelined grab: fetch next ticket before processing current pair.
        int pnext;
        if (lane == 0) pnext = atomicAdd(&d_work, 1);
        pnext = __shfl_sync(FULL, pnext, 0);

        int s = pid * 2 + half;
        if (s < ntot) {
            int slot, idx;
            const float *mu, *ch, *ft, *op;
            if (s < nl) { slot = 0; idx = s;      mu = lmu; ch = lch; ft = lft; op = lop; }
            else        { slot = 1; idx = s - nl; mu = hmu; ch = hch; ft = hft; op = hop; }

            float2 muv = ((const float2*)mu)[idx];
            float x = (tanhf(muv.x) + 1.0f) * 0.5f * (float)IMG_W;
            float y = (tanhf(muv.y) + 1.0f) * 0.5f * (float)IMG_H;

            float l1 = ch[idx * 3 + 0] + 0.5f;
            float l2 = ch[idx * 3 + 1];
            float l3 = ch[idx * 3 + 2] + 0.5f;
            float sxx = l1 * l1;
            float sxy = l1 * l2;
            float syy = l2 * l2 + l3 * l3;
            float det = sxx * syy - sxy * sxy;
            float inv = __fdividef(1.0f, det);
            float c0h = 0.5f * syy * inv;
            float c1  = -sxy * inv;
            float c2h = 0.5f * sxx * inv;

            float o  = op[idx];
            float cr = o * ft[idx * 3 + 0];
            float cg = o * ft[idx * 3 + 1];
            float cb = o * ft[idx * 3 + 2];

            float vx = fmaxf(2.0f * TCUT * sxx, 1e-12f);
            float vy = fmaxf(2.0f * TCUT * syy, 1e-12f);
            float rx = vx * rsqrtf(vx) + 0.02f;
            float ry = vy * rsqrtf(vy) + 0.02f;

            int x0 = max(0,         (int)ceilf (x - rx - 0.5f));
            int x1 = min(IMG_W - 1, (int)floorf(x + rx - 0.5f));
            int y0 = max(0,         (int)ceilf (y - ry - 0.5f));
            int y1 = min(IMG_H - 1, (int)floorf(y + ry - 0.5f));

            if (x0 <= x1 && y0 <= y1) {
                float4 fA = make_float4(0.f, 0.f, 0.f, 0.f);
                float4 fB = make_float4(0.f, 0.f, 0.f, 0.f);
                float4 wv = make_float4(0.f, 0.f, 0.f, 0.f);
                if (slot) {
                    const float4* fq = (const float4*)(gfreq + (size_t)idx * GAB * 2);
                    fA = fq[0];
                    fB = fq[1];
                    wv = ((const float4*)gwt)[idx];
                }

                int Wd = x1 - x0 + 1;
                int A  = Wd * (y1 - y0 + 1);
                for (int p = hlane; p < A; p += 16) {
                    int r = p / Wd;
                    int c = p - r * Wd;
                    int pxi = x0 + c;
                    int pyi = y0 + r;
                    float dx = (float)pxi + 0.5f - x;
                    float dy = (float)pyi + 0.5f - y;
                    float sig = c0h * dx * dx + c1 * dx * dy + c2h * dy * dy;
                    if (sig <= TCUT) {
                        float w = __expf(-sig);
                        if (slot) {
                            float mod = wv.x * __cosf(fA.x * dx + fA.y * dy)
                                      + wv.y * __cosf(fA.z * dx + fA.w * dy)
                                      + wv.z * __cosf(fB.x * dx + fB.y * dy)
                                      + wv.w * __cosf(fB.z * dx + fB.w * dy);
                            w *= mod;
                        }
                        red_add_v4(&d_acc[pyi * IMG_W + pxi], w * cr, w * cg, w * cb);
                    }
                }
            }
        }
        pid = pnext;
    }

    // ------------- Grid barrier: 32 distributed counters, lane-parallel poll ------------
    __threadfence();
    __syncthreads();
    if (tid == 0) {
        atomicAdd(&d_cnt32[blk & 31], 1);
    }
    if (tid < 32) {
        int sum;
        do {
            int v = *(volatile int*)&d_cnt32[lane];
            sum = __reduce_add_sync(0xffffffffu, v);
        } while (sum < NBLK);
    }
    __syncthreads();
    __threadfence();

    // All grabs happened before the barrier -> safe to reset the ticket counter here.
    if (blk == 0 && tid == 0) d_work = 0;

    // ------------- Phase 2: one pixel per thread: clip -> planar out, re-zero -----------
    {
        float4 a = d_acc[gtid];
        d_acc[gtid] = make_float4(0.f, 0.f, 0.f, 0.f);
        out[gtid]            = fminf(fmaxf(a.x, 0.f), 1.f);
        out[NPIX + gtid]     = fminf(fmaxf(a.y, 0.f), 1.f);
        out[2 * NPIX + gtid] = fminf(fmaxf(a.z, 0.f), 1.f);
    }

    // ------------- Reset barrier counters (last CTA out) --------------------------------
    if (tid == 0) {
        __threadfence();
        int v = atomicAdd(&d_done, 1);
        if (v == NBLK - 1) {
            #pragma unroll
            for (int i = 0; i < 32; i++) d_cnt32[i] = 0;
            d_done = 0;
            __threadfence();
        }
    }
}

extern "C" void kernel_launch(void* const* d_in, const int* in_sizes, int n_in,
                              void* d_out, int out_size)
{
    const float* low_mu    = (const float*)d_in[0];
    const float* high_mu   = (const float*)d_in[1];
    const float* low_chol  = (const float*)d_in[2];
    const float* high_chol = (const float*)d_in[3];
    const float* low_feat  = (const float*)d_in[4];
    const float* high_feat = (const float*)d_in[5];
    const float* low_opac  = (const float*)d_in[6];
    const float* high_opac = (const float*)d_in[7];
    const float* gfreq     = (const float*)d_in[8];
    const float* gwt       = (const float*)d_in[9];

    const int nl = in_sizes[6];
    const int nh = in_sizes[7];

    fused_splat_kernel<<<NBLK, NTHR>>>(low_mu, low_chol, low_feat, low_opac,
                                       high_mu, high_chol, high_feat, high_opac,
                                       gfreq, gwt, nl, nh, (float*)d_out);
}

// round 16
// speedup vs baseline: 1.4250x; 1.4250x over previous
#include <cuda_runtime.h>
#include <math.h>

#define IMG_W 256
#define IMG_H 256
#define NPIX  (IMG_W * IMG_H)
#define GAB   4
#define NBLK  128
#define NTHR  512
#define NWARP (NBLK * (NTHR / 32))   // 2048
#define TCUT  10.0f

// Static scratch — zero at module load; finalize_kernel restores zeros each run.
__device__ float4 d_acc[NPIX];       // RGBA accumulator (A unused)

__device__ __forceinline__ void red_add_v4(float4* addr, float r, float g, float b)
{
    asm volatile("red.global.add.v4.f32 [%0], {%1, %2, %3, %4};"
                 :: "l"(addr), "f"(r), "f"(g), "f"(b), "f"(0.0f)
                 : "memory");
}

__global__ __launch_bounds__(NTHR, 1)
void splat_kernel(const float* __restrict__ lmu, const float* __restrict__ lch,
                  const float* __restrict__ lft, const float* __restrict__ lop,
                  const float* __restrict__ hmu, const float* __restrict__ hch,
                  const float* __restrict__ hft, const float* __restrict__ hop,
                  const float* __restrict__ gfreq, const float* __restrict__ gwt,
                  int nl, int nh)
{
    const int tid   = threadIdx.x;
    const int blk   = blockIdx.x;
    const int lane  = tid & 31;
    const int half  = lane >> 4;
    const int hlane = lane & 15;
    const int gw    = blk * (NTHR / 32) + (tid >> 5);
    const int ntot  = nl + nh;
    const int npairs = (ntot + 1) >> 1;

    // Permuted pair id: spreads the heavy (gabor) tail pairs across all CTAs/warps.
    const int pid0 = ((gw & 7) << 8) | (gw >> 3);

    for (int pid = pid0; pid < npairs; pid += NWARP) {
        int s = pid * 2 + half;
        if (s < ntot) {
            int slot, idx;
            const float *mu, *ch, *ft, *op;
            if (s < nl) { slot = 0; idx = s;      mu = lmu; ch = lch; ft = lft; op = lop; }
            else        { slot = 1; idx = s - nl; mu = hmu; ch = hch; ft = hft; op = hop; }

            float2 muv = ((const float2*)mu)[idx];
            float x = (tanhf(muv.x) + 1.0f) * 0.5f * (float)IMG_W;
            float y = (tanhf(muv.y) + 1.0f) * 0.5f * (float)IMG_H;

            float l1 = ch[idx * 3 + 0] + 0.5f;
            float l2 = ch[idx * 3 + 1];
            float l3 = ch[idx * 3 + 2] + 0.5f;
            float sxx = l1 * l1;
            float sxy = l1 * l2;
            float syy = l2 * l2 + l3 * l3;
            float det = sxx * syy - sxy * sxy;
            float inv = __fdividef(1.0f, det);
            float c0h = 0.5f * syy * inv;
            float c1  = -sxy * inv;
            float c2h = 0.5f * sxx * inv;

            float o  = op[idx];
            float cr = o * ft[idx * 3 + 0];
            float cg = o * ft[idx * 3 + 1];
            float cb = o * ft[idx * 3 + 2];

            float vx = fmaxf(2.0f * TCUT * sxx, 1e-12f);
            float vy = fmaxf(2.0f * TCUT * syy, 1e-12f);
            float rx = vx * rsqrtf(vx) + 0.02f;
            float ry = vy * rsqrtf(vy) + 0.02f;

            int x0 = max(0,         (int)ceilf (x - rx - 0.5f));
            int x1 = min(IMG_W - 1, (int)floorf(x + rx - 0.5f));
            int y0 = max(0,         (int)ceilf (y - ry - 0.5f));
            int y1 = min(IMG_H - 1, (int)floorf(y + ry - 0.5f));

            if (x0 <= x1 && y0 <= y1) {
                float4 fA = make_float4(0.f, 0.f, 0.f, 0.f);
                float4 fB = make_float4(0.f, 0.f, 0.f, 0.f);
                float4 wv = make_float4(0.f, 0.f, 0.f, 0.f);
                if (slot) {
                    const float4* fq = (const float4*)(gfreq + (size_t)idx * GAB * 2);
                    fA = fq[0];
                    fB = fq[1];
                    wv = ((const float4*)gwt)[idx];
                }

                int Wd = x1 - x0 + 1;
                int A  = Wd * (y1 - y0 + 1);
                for (int p = hlane; p < A; p += 16) {
                    int r = p / Wd;
                    int c = p - r * Wd;
                    int pxi = x0 + c;
                    int pyi = y0 + r;
                    float dx = (float)pxi + 0.5f - x;
                    float dy = (float)pyi + 0.5f - y;
                    float sig = c0h * dx * dx + c1 * dx * dy + c2h * dy * dy;
                    if (sig <= TCUT) {
                        float w = __expf(-sig);
                        if (slot) {
                            float mod = wv.x * __cosf(fA.x * dx + fA.y * dy)
                                      + wv.y * __cosf(fA.z * dx + fA.w * dy)
                                      + wv.z * __cosf(fB.x * dx + fB.y * dy)
                                      + wv.w * __cosf(fB.z * dx + fB.w * dy);
                            w *= mod;
                        }
                        red_add_v4(&d_acc[pyi * IMG_W + pxi], w * cr, w * cg, w * cb);
                    }
                }
            }
        }
    }
}

__global__ __launch_bounds__(256, 8)
void finalize_kernel(float* __restrict__ out)
{
    const int g = blockIdx.x * 256 + threadIdx.x;   // one pixel per thread (65536)
    float4 a = d_acc[g];
    d_acc[g] = make_float4(0.f, 0.f, 0.f, 0.f);
    out[g]            = fminf(fmaxf(a.x, 0.f), 1.f);
    out[NPIX + g]     = fminf(fmaxf(a.y, 0.f), 1.f);
    out[2 * NPIX + g] = fminf(fmaxf(a.z, 0.f), 1.f);
}

extern "C" void kernel_launch(void* const* d_in, const int* in_sizes, int n_in,
                              void* d_out, int out_size)
{
    const float* low_mu    = (const float*)d_in[0];
    const float* high_mu   = (const float*)d_in[1];
    const float* low_chol  = (const float*)d_in[2];
    const float* high_chol = (const float*)d_in[3];
    const float* low_feat  = (const float*)d_in[4];
    const float* high_feat = (const float*)d_in[5];
    const float* low_opac  = (const float*)d_in[6];
    const float* high_opac = (const float*)d_in[7];
    const float* gfreq     = (const float*)d_in[8];
    const float* gwt       = (const float*)d_in[9];

    const int nl = in_sizes[6];
    const int nh = in_sizes[7];

    splat_kernel<<<NBLK, NTHR>>>(low_mu, low_chol, low_feat, low_opac,
                                 high_mu, high_chol, high_feat, high_opac,
                                 gfreq, gwt, nl, nh);

    finalize_kernel<<<NPIX / 256, 256>>>((float*)d_out);
}

// round 17
// speedup vs baseline: 1.4301x; 1.0036x over previous
#include <cuda_runtime.h>
#include <math.h>

#define IMG_W 256
#define IMG_H 256
#define NPIX  (IMG_W * IMG_H)
#define GAB   4
#define NBLK  128
#define NTHR  512
#define NWARP (NBLK * (NTHR / 32))   // 2048
#define TCUT  10.0f

// Static scratch — zero at module load; finalize_kernel restores zeros each run.
__device__ float4 d_acc[NPIX];       // RGBA accumulator (A unused)

__device__ __forceinline__ void red_add_v4(float4* addr, float r, float g, float b)
{
    asm volatile("red.global.add.v4.f32 [%0], {%1, %2, %3, %4};"
                 :: "l"(addr), "f"(r), "f"(g), "f"(b), "f"(0.0f)
                 : "memory");
}

__global__ __launch_bounds__(NTHR, 1)
void splat_kernel(const float* __restrict__ lmu, const float* __restrict__ lch,
                  const float* __restrict__ lft, const float* __restrict__ lop,
                  const float* __restrict__ hmu, const float* __restrict__ hch,
                  const float* __restrict__ hft, const float* __restrict__ hop,
                  const float* __restrict__ gfreq, const float* __restrict__ gwt,
                  int nl, int nh)
{
    const int tid   = threadIdx.x;
    const int blk   = blockIdx.x;
    const int lane  = tid & 31;
    const int half  = lane >> 4;
    const int hlane = lane & 15;
    const int gw    = blk * (NTHR / 32) + (tid >> 5);
    const int ntot  = nl + nh;
    const int npairs = (ntot + 1) >> 1;

    // Permuted pair id: spreads the heavy (gabor) tail pairs across all CTAs/warps.
    const int pid0 = ((gw & 7) << 8) | (gw >> 3);

    for (int pid = pid0; pid < npairs; pid += NWARP) {
        int s = pid * 2 + half;
        if (s < ntot) {
            int slot, idx;
            const float *mu, *ch, *ft, *op;
            if (s < nl) { slot = 0; idx = s;      mu = lmu; ch = lch; ft = lft; op = lop; }
            else        { slot = 1; idx = s - nl; mu = hmu; ch = hch; ft = hft; op = hop; }

            float2 muv = ((const float2*)mu)[idx];
            float x = (tanhf(muv.x) + 1.0f) * 0.5f * (float)IMG_W;
            float y = (tanhf(muv.y) + 1.0f) * 0.5f * (float)IMG_H;

            float l1 = ch[idx * 3 + 0] + 0.5f;
            float l2 = ch[idx * 3 + 1];
            float l3 = ch[idx * 3 + 2] + 0.5f;
            float sxx = l1 * l1;
            float sxy = l1 * l2;
            float syy = l2 * l2 + l3 * l3;
            float det = sxx * syy - sxy * sxy;
            float inv = __fdividef(1.0f, det);
            float c0h = 0.5f * syy * inv;
            float c1  = -sxy * inv;
            float c2h = 0.5f * sxx * inv;

            float o  = op[idx];
            float cr = o * ft[idx * 3 + 0];
            float cg = o * ft[idx * 3 + 1];
            float cb = o * ft[idx * 3 + 2];

            float vx = fmaxf(2.0f * TCUT * sxx, 1e-12f);
            float vy = fmaxf(2.0f * TCUT * syy, 1e-12f);
            float rx = vx * rsqrtf(vx) + 0.02f;
            float ry = vy * rsqrtf(vy) + 0.02f;

            int x0 = max(0,         (int)ceilf (x - rx - 0.5f));
            int x1 = min(IMG_W - 1, (int)floorf(x + rx - 0.5f));
            int y0 = max(0,         (int)ceilf (y - ry - 0.5f));
            int y1 = min(IMG_H - 1, (int)floorf(y + ry - 0.5f));

            if (x0 <= x1 && y0 <= y1) {
                float4 fA = make_float4(0.f, 0.f, 0.f, 0.f);
                float4 fB = make_float4(0.f, 0.f, 0.f, 0.f);
                float4 wv = make_float4(0.f, 0.f, 0.f, 0.f);
                if (slot) {
                    const float4* fq = (const float4*)(gfreq + (size_t)idx * GAB * 2);
                    fA = fq[0];
                    fB = fq[1];
                    wv = ((const float4*)gwt)[idx];
                }

                int Wd = x1 - x0 + 1;
                int A  = Wd * (y1 - y0 + 1);
                for (int p = hlane; p < A; p += 16) {
                    int r = p / Wd;
                    int c = p - r * Wd;
                    int pxi = x0 + c;
                    int pyi = y0 + r;
                    float dx = (float)pxi + 0.5f - x;
                    float dy = (float)pyi + 0.5f - y;
                    float sig = c0h * dx * dx + c1 * dx * dy + c2h * dy * dy;
                    if (sig <= TCUT) {
                        float w = __expf(-sig);
                        if (slot) {
                            float mod = wv.x * __cosf(fA.x * dx + fA.y * dy)
                                      + wv.y * __cosf(fA.z * dx + fA.w * dy)
                                      + wv.z * __cosf(fB.x * dx + fB.y * dy)
                                      + wv.w * __cosf(fB.z * dx + fB.w * dy);
                            w *= mod;
                        }
                        red_add_v4(&d_acc[pyi * IMG_W + pxi], w * cr, w * cg, w * cb);
                    }
                }
            }
        }
    }
}

__device__ __forceinline__ float clip01(float v) { return fminf(fmaxf(v, 0.f), 1.f); }

__global__ __launch_bounds__(256, 8)
void finalize_kernel(float* __restrict__ out)
{
    // PDL: prelaunched while splat_kernel still runs; blocks here until it
    // fully completes (implicit trigger => all red.global results visible).
    cudaGridDependencySynchronize();

    const int g = blockIdx.x * 256 + threadIdx.x;   // 16384 threads, 4 pixels each
    const int base = g * 4;

    float4 a0 = d_acc[base + 0];
    float4 a1 = d_acc[base + 1];
    float4 a2 = d_acc[base + 2];
    float4 a3 = d_acc[base + 3];

    const float4 z = make_float4(0.f, 0.f, 0.f, 0.f);
    d_acc[base + 0] = z;
    d_acc[base + 1] = z;
    d_acc[base + 2] = z;
    d_acc[base + 3] = z;

    float4* out4 = (float4*)out;
    out4[g]                 = make_float4(clip01(a0.x), clip01(a1.x), clip01(a2.x), clip01(a3.x));
    out4[(NPIX / 4) + g]     = make_float4(clip01(a0.y), clip01(a1.y), clip01(a2.y), clip01(a3.y));
    out4[(NPIX / 2) + g]     = make_float4(clip01(a0.z), clip01(a1.z), clip01(a2.z), clip01(a3.z));
}

extern "C" void kernel_launch(void* const* d_in, const int* in_sizes, int n_in,
                              void* d_out, int out_size)
{
    const float* low_mu    = (const float*)d_in[0];
    const float* high_mu   = (const float*)d_in[1];
    const float* low_chol  = (const float*)d_in[2];
    const float* high_chol = (const float*)d_in[3];
    const float* low_feat  = (const float*)d_in[4];
    const float* high_feat = (const float*)d_in[5];
    const float* low_opac  = (const float*)d_in[6];
    const float* high_opac = (const float*)d_in[7];
    const float* gfreq     = (const float*)d_in[8];
    const float* gwt       = (const float*)d_in[9];

    const int nl = in_sizes[6];
    const int nh = in_sizes[7];

    splat_kernel<<<NBLK, NTHR>>>(low_mu, low_chol, low_feat, low_opac,
                                 high_mu, high_chol, high_feat, high_opac,
                                 gfreq, gwt, nl, nh);

    // Finalize with Programmatic Dependent Launch: overlap its launch/setup
    // with the tail of splat_kernel; gridsync inside enforces the dependency.
    cudaLaunchConfig_t cfg = {};
    cfg.gridDim  = dim3(NPIX / 4 / 256);   // 64 blocks
    cfg.blockDim = dim3(256);
    cfg.dynamicSmemBytes = 0;
    cfg.stream = 0;
    cudaLaunchAttribute attrs[1];
    attrs[0].id = cudaLaunchAttributeProgrammaticStreamSerialization;
    attrs[0].val.programmaticStreamSerializationAllowed = 1;
    cfg.attrs = attrs;
    cfg.numAttrs = 1;
    cudaLaunchKernelEx(&cfg, finalize_kernel, (float*)d_out);
}